// round 7
// baseline (speedup 1.0000x reference)
#include <cuda_runtime.h>
#include <cuda_fp16.h>
#include <cstdint>

// Shapes (fixed for KANLayer_17265768530645)
#define B_SZ    8192
#define D_IN    512
#define D_OUT   128
#define X_MIN_F (-3.0f)
#define DENOM   6.00000001f
#define SCALE_F (15.0f / DENOM)

// GEMM: y[b,n] = sum_{k'} C[b,k'] * W'[n,k'],  K' = 8704
//   k' in [0,8192):    C = hat pair {1-f, f} at (16i+k0, 16i+k0+1), W' = w[n, k']
//   k' in [8192,8704): C = x[b, k'-8192],                           W' = skip[n, .]
#define KSTEPS   544          // K'/16
#define NCHUNK   68           // K'/128

// W' pre-packed as per-lane mma B-fragments.
// Index: ((wc*KSTEPS + ks)*2 + h)*32 + lane   (uint4; h=0 -> nfrag 0,1; h=1 -> 2,3)
__device__ __align__(16) uint4 g_wf[4 * KSTEPS * 2 * 32];   // 2.2 MB

// ---------------- PTX helpers (baseline sm_80-era, no 'a' features) --------
__device__ __forceinline__ void ldm4(uint32_t* a, uint32_t addr) {
    asm volatile("ldmatrix.sync.aligned.m8n8.x4.shared.b16 {%0,%1,%2,%3}, [%4];"
                 : "=r"(a[0]), "=r"(a[1]), "=r"(a[2]), "=r"(a[3]) : "r"(addr));
}
__device__ __forceinline__ void mma16816(float* c, const uint32_t* a,
                                         uint32_t b0, uint32_t b1) {
    asm volatile(
        "mma.sync.aligned.m16n8k16.row.col.f32.f16.f16.f32 "
        "{%0,%1,%2,%3}, {%4,%5,%6,%7}, {%8,%9}, {%0,%1,%2,%3};"
        : "+f"(c[0]), "+f"(c[1]), "+f"(c[2]), "+f"(c[3])
        : "r"(a[0]), "r"(a[1]), "r"(a[2]), "r"(a[3]), "r"(b0), "r"(b1));
}
__device__ __forceinline__ uint32_t h2u(__half2 h) {
    return *reinterpret_cast<uint32_t*>(&h);
}

// ---------------------------------------------------------------------------
// W' prep: gather fp32 weights/skip into fp16 mma B-fragment layout.
// grid (136, 4), block 128: ks = bx*4 + (t>>5), wc = by, lane = t&31.
// Fragment mapping (m16n8k16 .col B): n = wc*32 + nf*8 + lane/4,
// k-pair = ks*16 + (lane%4)*2 + {0,1} (+8 for second reg).
// ---------------------------------------------------------------------------
__global__ void kan_wprep(const float* __restrict__ w,    // (128, 512, 16)
                          const float* __restrict__ s)    // (128, 512)
{
    const int wc   = blockIdx.y;
    const int lane = threadIdx.x & 31;
    const int ks   = blockIdx.x * 4 + (threadIdx.x >> 5);

    uint32_t r[8];
    #pragma unroll
    for (int nf = 0; nf < 4; nf++) {
        const int n = wc * 32 + nf * 8 + (lane >> 2);
        #pragma unroll
        for (int h = 0; h < 2; h++) {
            const int k = ks * 16 + (lane & 3) * 2 + h * 8;
            float v0, v1;
            if (ks < 512) {                 // spline region: W'[n,k] = w[n*8192+k]
                v0 = w[(size_t)n * 8192 + k];
                v1 = w[(size_t)n * 8192 + k + 1];
            } else {                        // skip region
                const int kk = k - 8192;
                v0 = s[(size_t)n * 512 + kk];
                v1 = s[(size_t)n * 512 + kk + 1];
            }
            r[nf * 2 + h] = h2u(__floats2half2_rn(v0, v1));
        }
    }
    g_wf[((size_t)(wc * KSTEPS + ks) * 2 + 0) * 32 + lane] = make_uint4(r[0], r[1], r[2], r[3]);
    g_wf[((size_t)(wc * KSTEPS + ks) * 2 + 1) * 32 + lane] = make_uint4(r[4], r[5], r[6], r[7]);
}

// ---------------------------------------------------------------------------
// Main GEMM: grid 128, block 256. CTA = 64 b-rows x 128 outputs, full K'.
// Warp grid 2(M) x 4(N); warp tile 32x32. C chunk (64x128 fp16) built in SMEM
// with XOR swizzle: byte(b, cb) = b*256 + (cb ^ ((b&7)<<5)).
// ---------------------------------------------------------------------------
__global__ __launch_bounds__(256)
void kan_mma(const float* __restrict__ x,
             const float* __restrict__ bias,
             float* __restrict__ y)
{
    __shared__ __align__(16) char cs[64 * 256];   // 16 KB C chunk

    const int tid  = threadIdx.x;
    const int lane = tid & 31;
    const int w    = tid >> 5;
    const int wm   = w >> 2;          // 0..1  (M warp row)
    const int wc   = w & 3;           // 0..3  (N warp col)
    const int bt   = blockIdx.x;      // b-tile 0..127

    // Accumulators, bias-initialized. acc[mf][nf][0..3]
    float acc[2][4][4];
    #pragma unroll
    for (int nf = 0; nf < 4; nf++) {
        const int n0 = wc * 32 + nf * 8 + (lane & 3) * 2;
        const float b0 = bias[n0], b1 = bias[n0 + 1];
        #pragma unroll
        for (int mf = 0; mf < 2; mf++) {
            acc[mf][nf][0] = b0; acc[mf][nf][1] = b1;
            acc[mf][nf][2] = b0; acc[mf][nf][3] = b1;
        }
    }

    // ldmatrix per-thread base addresses (A fragments)
    const uint32_t cs32 = (uint32_t)__cvta_generic_to_shared(cs);
    const int arow  = wm * 32 + (lane & 15);
    const uint32_t swz   = (uint32_t)((lane & 7) << 5);
    const uint32_t abase0 = cs32 + arow * 256 + ((lane >> 4) << 4);
    const uint32_t abase1 = abase0 + 16 * 256;

    // B fragment stream for this warp column
    const uint4* wp = g_wf + (size_t)wc * KSTEPS * 64 + lane;

    // Build-thread mapping: b = tid/4, q = tid%4
    const int bb = tid >> 2, q = tid & 3;
    char* rb = cs + bb * 256;
    const uint32_t swb = (uint32_t)((bb & 7) << 5);
    const float* xrow = x + (size_t)(bt * 64 + bb) * 512;

    for (int ch = 0; ch < NCHUNK; ch++) {
        __syncthreads();   // previous chunk fully consumed
        if (ch < 64) {
            // spline chunk: i = ch*8 + il, il = q*2 + e
            float2 xv = *reinterpret_cast<const float2*>(xrow + ch * 8 + q * 2);
            #pragma unroll
            for (int e = 0; e < 2; e++) {
                const float xx = e ? xv.y : xv.x;
                const int il = q * 2 + e;
                float p = fminf(fmaxf((xx - X_MIN_F) * SCALE_F, 0.0f), 15.0f);
                int   k0 = min((int)p, 14);
                float f  = p - (float)k0;
                *reinterpret_cast<uint4*>(rb + ((il * 32)      ^ swb)) = make_uint4(0, 0, 0, 0);
                *reinterpret_cast<uint4*>(rb + ((il * 32 + 16) ^ swb)) = make_uint4(0, 0, 0, 0);
                const uint32_t cb = (uint32_t)(il * 32 + k0 * 2);
                *reinterpret_cast<__half*>(rb + (cb ^ swb))       = __float2half_rn(1.0f - f);
                *reinterpret_cast<__half*>(rb + ((cb + 2) ^ swb)) = __float2half_rn(f);
            }
        } else {
            // skip chunk: C = x features (fp16), 32 cols per thread
            const float* xp = xrow + (ch - 64) * 128 + q * 32;
            #pragma unroll
            for (int v = 0; v < 4; v++) {
                float4 f0 = *reinterpret_cast<const float4*>(xp + v * 8);
                float4 f1 = *reinterpret_cast<const float4*>(xp + v * 8 + 4);
                uint4 pk = make_uint4(h2u(__floats2half2_rn(f0.x, f0.y)),
                                      h2u(__floats2half2_rn(f0.z, f0.w)),
                                      h2u(__floats2half2_rn(f1.x, f1.y)),
                                      h2u(__floats2half2_rn(f1.z, f1.w)));
                *reinterpret_cast<uint4*>(rb + ((q * 64 + v * 16) ^ swb)) = pk;
            }
        }
        __syncthreads();   // chunk ready

        #pragma unroll
        for (int ksl = 0; ksl < 8; ksl++) {
            const int ks = ch * 8 + ksl;
            const uint4 q0 = wp[(size_t)ks * 64];
            const uint4 q1 = wp[(size_t)ks * 64 + 32];
            const uint32_t koff = ((uint32_t)(ksl * 32)) ^ swz;

            uint32_t a[4];
            ldm4(a, abase0 + koff);
            mma16816(acc[0][0], a, q0.x, q0.y);
            mma16816(acc[0][1], a, q0.z, q0.w);
            mma16816(acc[0][2], a, q1.x, q1.y);
            mma16816(acc[0][3], a, q1.z, q1.w);

            ldm4(a, abase1 + koff);
            mma16816(acc[1][0], a, q0.x, q0.y);
            mma16816(acc[1][1], a, q0.z, q0.w);
            mma16816(acc[1][2], a, q1.x, q1.y);
            mma16816(acc[1][3], a, q1.z, q1.w);
        }
    }

    // Epilogue: write fp32 outputs (bias already folded).
    float* yb = y + (size_t)(bt * 64 + wm * 32) * 128;
    #pragma unroll
    for (int mf = 0; mf < 2; mf++) {
        const int r0 = mf * 16 + (lane >> 2);
        #pragma unroll
        for (int nf = 0; nf < 4; nf++) {
            const int n0 = wc * 32 + nf * 8 + (lane & 3) * 2;
            *reinterpret_cast<float2*>(yb + (size_t)r0 * 128 + n0) =
                make_float2(acc[mf][nf][0], acc[mf][nf][1]);
            *reinterpret_cast<float2*>(yb + (size_t)(r0 + 8) * 128 + n0) =
                make_float2(acc[mf][nf][2], acc[mf][nf][3]);
        }
    }
}

// ---------------------------------------------------------------------------
// kernel_launch: inputs per metadata order: x, weights, skip_w, bias
// ---------------------------------------------------------------------------
extern "C" void kernel_launch(void* const* d_in, const int* in_sizes, int n_in,
                              void* d_out, int out_size)
{
    const float* x    = (const float*)d_in[0];
    const float* w    = (const float*)d_in[1];
    const float* skip = (const float*)d_in[2];
    const float* bias = (const float*)d_in[3];
    float* y = (float*)d_out;

    kan_wprep<<<dim3(136, 4), 128>>>(w, skip);
    kan_mma<<<128, 256>>>(x, bias, y);
}

// round 8
// speedup vs baseline: 1.5367x; 1.5367x over previous
#include <cuda_runtime.h>
#include <cuda_fp16.h>
#include <cstdint>

// Shapes (fixed for KANLayer_17265768530645)
#define B_SZ    8192
#define D_IN    512
#define D_OUT   128
#define X_MIN_F (-3.0f)
#define DENOM   6.00000001f
#define SCALE_F (15.0f / DENOM)

// GEMM: y[b,n] = sum_{k'} C[b,k'] * W'[n,k'],  K' = 8704
//   k' in [0,8192):    C = hat pair {1-f, f} at (16i+k0, 16i+k0+1), W' = w[n, k']
//   k' in [8192,8704): C = x[b, k'-8192],                           W' = skip[n, .]
#define KSTEPS   544          // K'/16
#define NCHUNK   68           // K'/128

// W' pre-packed as per-lane mma B-fragments.
// Index: ((wc*KSTEPS + ks)*2 + h)*32 + lane
__device__ __align__(16) uint4 g_wf[4 * KSTEPS * 2 * 32];   // 2.2 MB

// ---------------- PTX helpers (baseline, no 'a'-suffix features) -----------
__device__ __forceinline__ void ldm4(uint32_t* a, uint32_t addr) {
    asm volatile("ldmatrix.sync.aligned.m8n8.x4.shared.b16 {%0,%1,%2,%3}, [%4];"
                 : "=r"(a[0]), "=r"(a[1]), "=r"(a[2]), "=r"(a[3]) : "r"(addr));
}
__device__ __forceinline__ void mma16816(float* c, const uint32_t* a,
                                         uint32_t b0, uint32_t b1) {
    asm volatile(
        "mma.sync.aligned.m16n8k16.row.col.f32.f16.f16.f32 "
        "{%0,%1,%2,%3}, {%4,%5,%6,%7}, {%8,%9}, {%0,%1,%2,%3};"
        : "+f"(c[0]), "+f"(c[1]), "+f"(c[2]), "+f"(c[3])
        : "r"(a[0]), "r"(a[1]), "r"(a[2]), "r"(a[3]), "r"(b0), "r"(b1));
}
__device__ __forceinline__ uint32_t h2u(__half2 h) {
    return *reinterpret_cast<uint32_t*>(&h);
}

// ---------------------------------------------------------------------------
// W' prep (unchanged from R7; validated).
// ---------------------------------------------------------------------------
__global__ void kan_wprep(const float* __restrict__ w,    // (128, 512, 16)
                          const float* __restrict__ s)    // (128, 512)
{
    const int wc   = blockIdx.y;
    const int lane = threadIdx.x & 31;
    const int ks   = blockIdx.x * 4 + (threadIdx.x >> 5);

    uint32_t r[8];
    #pragma unroll
    for (int nf = 0; nf < 4; nf++) {
        const int n = wc * 32 + nf * 8 + (lane >> 2);
        #pragma unroll
        for (int h = 0; h < 2; h++) {
            const int k = ks * 16 + (lane & 3) * 2 + h * 8;
            float v0, v1;
            if (ks < 512) {
                v0 = w[(size_t)n * 8192 + k];
                v1 = w[(size_t)n * 8192 + k + 1];
            } else {
                const int kk = k - 8192;
                v0 = s[(size_t)n * 512 + kk];
                v1 = s[(size_t)n * 512 + kk + 1];
            }
            r[nf * 2 + h] = h2u(__floats2half2_rn(v0, v1));
        }
    }
    g_wf[((size_t)(wc * KSTEPS + ks) * 2 + 0) * 32 + lane] = make_uint4(r[0], r[1], r[2], r[3]);
    g_wf[((size_t)(wc * KSTEPS + ks) * 2 + 1) * 32 + lane] = make_uint4(r[4], r[5], r[6], r[7]);
}

// ---------------------------------------------------------------------------
// C-chunk builders. Swizzle: byte(b, cb) = b*256 + (cb ^ ((b&7)<<5)).
// ---------------------------------------------------------------------------
__device__ __forceinline__ void build_spline(char* rb, uint32_t swb,
                                             float xa, float xb, int q)
{
    #pragma unroll
    for (int e = 0; e < 2; e++) {
        const float xx = e ? xb : xa;
        const int il = q * 2 + e;
        float p = fminf(fmaxf((xx - X_MIN_F) * SCALE_F, 0.0f), 15.0f);
        int   k0 = min((int)p, 14);
        float f  = p - (float)k0;
        *reinterpret_cast<uint4*>(rb + ((uint32_t)(il * 32)      ^ swb)) = make_uint4(0,0,0,0);
        *reinterpret_cast<uint4*>(rb + ((uint32_t)(il * 32 + 16) ^ swb)) = make_uint4(0,0,0,0);
        const uint32_t cb = (uint32_t)(il * 32 + k0 * 2);
        *reinterpret_cast<__half*>(rb + (cb ^ swb))       = __float2half_rn(1.0f - f);
        *reinterpret_cast<__half*>(rb + ((cb + 2) ^ swb)) = __float2half_rn(f);
    }
}

__device__ __forceinline__ void build_skip(char* rb, uint32_t swb,
                                           const float* __restrict__ xp, int q)
{
    #pragma unroll
    for (int v = 0; v < 4; v++) {
        float4 f0 = *reinterpret_cast<const float4*>(xp + v * 8);
        float4 f1 = *reinterpret_cast<const float4*>(xp + v * 8 + 4);
        uint4 pk = make_uint4(h2u(__floats2half2_rn(f0.x, f0.y)),
                              h2u(__floats2half2_rn(f0.z, f0.w)),
                              h2u(__floats2half2_rn(f1.x, f1.y)),
                              h2u(__floats2half2_rn(f1.z, f1.w)));
        *reinterpret_cast<uint4*>(rb + ((uint32_t)(q * 64 + v * 16) ^ swb)) = pk;
    }
}

// ---------------------------------------------------------------------------
// Main GEMM: grid 128, block 256. CTA = 64 b-rows x 128 outputs, full K'.
// Double-buffered C chunk; depth-2 B-fragment register prefetch; x prefetch.
// ---------------------------------------------------------------------------
__global__ __launch_bounds__(256)
void kan_mma(const float* __restrict__ x,
             const float* __restrict__ bias,
             float* __restrict__ y)
{
    __shared__ __align__(16) char cs[2][64 * 256];   // 32 KB

    const int tid  = threadIdx.x;
    const int lane = tid & 31;
    const int w    = tid >> 5;
    const int wm   = w >> 2;
    const int wc   = w & 3;
    const int bt   = blockIdx.x;

    float acc[2][4][4];
    #pragma unroll
    for (int nf = 0; nf < 4; nf++) {
        const int n0 = wc * 32 + nf * 8 + (lane & 3) * 2;
        const float b0 = bias[n0], b1 = bias[n0 + 1];
        #pragma unroll
        for (int mf = 0; mf < 2; mf++) {
            acc[mf][nf][0] = b0; acc[mf][nf][1] = b1;
            acc[mf][nf][2] = b0; acc[mf][nf][3] = b1;
        }
    }

    const uint32_t cs32 = (uint32_t)__cvta_generic_to_shared(cs);
    const int arow  = wm * 32 + (lane & 15);
    const uint32_t swz = (uint32_t)((lane & 7) << 5);
    const uint32_t aoff = (uint32_t)(arow * 256 + ((lane >> 4) << 4));

    const uint4* wp = g_wf + (size_t)wc * KSTEPS * 64 + lane;

    const int bb = tid >> 2, q = tid & 3;
    const uint32_t swb = (uint32_t)((bb & 7) << 5);
    const float* xrow = x + (size_t)(bt * 64 + bb) * 512;

    // B prefetch ring (depth 2): slot ks&1 holds k-step ks.
    uint4 bq[2][2];
    bq[0][0] = wp[0];  bq[0][1] = wp[32];
    bq[1][0] = wp[64]; bq[1][1] = wp[96];

    // Build chunk 0 (overlaps with the B prefetch LDGs above).
    {
        float2 xv = *reinterpret_cast<const float2*>(xrow + q * 2);
        build_spline(cs[0] + bb * 256, swb, xv.x, xv.y, q);
    }
    __syncthreads();

    for (int ch = 0; ch < NCHUNK; ch++) {
        const int cur = ch & 1, nxt = cur ^ 1;

        // Prefetch x for next chunk's build (spline chunks only).
        float2 xpre = make_float2(0.f, 0.f);
        const bool haveNext  = (ch + 1 < NCHUNK);
        const bool nextSplin = (ch + 1 < 64);
        if (haveNext && nextSplin)
            xpre = *reinterpret_cast<const float2*>(xrow + (ch + 1) * 8 + q * 2);

        const uint32_t abase0 = cs32 + (uint32_t)cur * 16384 + aoff;
        const uint32_t abase1 = abase0 + 16 * 256;

        #pragma unroll
        for (int ksl = 0; ksl < 8; ksl++) {
            const int ks = ch * 8 + ksl;
            const int slot = ks & 1;
            const uint4 q0 = bq[slot][0];
            const uint4 q1 = bq[slot][1];
            if (ks + 2 < KSTEPS) {
                bq[slot][0] = wp[(size_t)(ks + 2) * 64];
                bq[slot][1] = wp[(size_t)(ks + 2) * 64 + 32];
            }
            const uint32_t koff = ((uint32_t)(ksl * 32)) ^ swz;

            uint32_t a[4];
            ldm4(a, abase0 + koff);
            mma16816(acc[0][0], a, q0.x, q0.y);
            mma16816(acc[0][1], a, q0.z, q0.w);
            mma16816(acc[0][2], a, q1.x, q1.y);
            mma16816(acc[0][3], a, q1.z, q1.w);

            ldm4(a, abase1 + koff);
            mma16816(acc[1][0], a, q0.x, q0.y);
            mma16816(acc[1][1], a, q0.z, q0.w);
            mma16816(acc[1][2], a, q1.x, q1.y);
            mma16816(acc[1][3], a, q1.z, q1.w);
        }

        // Build next chunk into the other buffer (overlapped w.r.t. barriers).
        if (haveNext) {
            char* rb = cs[nxt] + bb * 256;
            if (nextSplin) {
                build_spline(rb, swb, xpre.x, xpre.y, q);
            } else {
                build_skip(rb, swb, xrow + (ch + 1 - 64) * 128 + q * 32, q);
            }
        }
        __syncthreads();
    }

    // Epilogue: fp32 outputs (bias folded in accumulator init).
    float* yb = y + (size_t)(bt * 64 + wm * 32) * 128;
    #pragma unroll
    for (int mf = 0; mf < 2; mf++) {
        const int r0 = mf * 16 + (lane >> 2);
        #pragma unroll
        for (int nf = 0; nf < 4; nf++) {
            const int n0 = wc * 32 + nf * 8 + (lane & 3) * 2;
            *reinterpret_cast<float2*>(yb + (size_t)r0 * 128 + n0) =
                make_float2(acc[mf][nf][0], acc[mf][nf][1]);
            *reinterpret_cast<float2*>(yb + (size_t)(r0 + 8) * 128 + n0) =
                make_float2(acc[mf][nf][2], acc[mf][nf][3]);
        }
    }
}

// ---------------------------------------------------------------------------
// kernel_launch: inputs per metadata order: x, weights, skip_w, bias
// ---------------------------------------------------------------------------
extern "C" void kernel_launch(void* const* d_in, const int* in_sizes, int n_in,
                              void* d_out, int out_size)
{
    const float* x    = (const float*)d_in[0];
    const float* w    = (const float*)d_in[1];
    const float* skip = (const float*)d_in[2];
    const float* bias = (const float*)d_in[3];
    float* y = (float*)d_out;

    kan_wprep<<<dim3(136, 4), 128>>>(w, skip);
    kan_mma<<<128, 256>>>(x, bias, y);
}